// round 3
// baseline (speedup 1.0000x reference)
#include <cuda_runtime.h>
#include <math.h>

typedef unsigned long long ull;

#define SL 36
#define TL 20
#define SENT (1u << 19)
#define TENT (1u << 17)
#define SMASK (SENT - 1u)
#define TMASK (TENT - 1u)
#define HID 128
#define ENC 112
#define NSLOT (SL + TL)   // 56
#define P 32              // points per MLP block
#define NT 128            // threads per MLP block
#define RS 36             // smem row stride (floats)
#define MAXB 131072

// global scratch: features, k-major [ENC][MAXB]
__device__ __align__(16) float g_feats[ENC * MAXB];

// ---- packed fp32x2 helpers (sm_103a FFMA2 path) -----------------------------
__device__ __forceinline__ ull splat2(float v) {
    ull r; asm("mov.b64 %0, {%1, %1};" : "=l"(r) : "f"(v)); return r;
}
__device__ __forceinline__ ull pack2(float a, float b) {
    ull r; asm("mov.b64 %0, {%1, %2};" : "=l"(r) : "f"(a), "f"(b)); return r;
}
__device__ __forceinline__ float2 unpack2(ull v) {
    float2 r; asm("mov.b64 {%0, %1}, %2;" : "=f"(r.x), "=f"(r.y) : "l"(v)); return r;
}
__device__ __forceinline__ ull fma2(ull a, ull b, ull c) {
    ull d; asm("fma.rn.f32x2 %0, %1, %2, %3;" : "=l"(d) : "l"(a), "l"(b), "l"(c)); return d;
}
__device__ __forceinline__ ull mul2(ull a, ull b) {
    ull d; asm("mul.rn.f32x2 %0, %1, %2;" : "=l"(d) : "l"(a), "l"(b)); return d;
}

// ============================================================================
// Kernel 1: hash-grid encode. 256 threads, 32 points/block, lane = point,
// warp-uniform level s = w + 8*i. Output streamed to g_feats (k-major).
// ============================================================================
__global__ __launch_bounds__(256)
void encode_kernel(const float4* __restrict__ coords,
                   const float2* __restrict__ stab,
                   const float2* __restrict__ ttab,
                   int B)
{
    __shared__ float ress[NSLOT];
    const int tid  = threadIdx.x;
    const int w    = tid >> 5;
    const int lane = tid & 31;

    if (tid < SL) {
        ress[tid] = floorf(16.0f * (float)pow((double)1.38f, (double)tid));
    } else if (tid < NSLOT) {
        ress[tid] = floorf(16.0f * (float)pow((double)1.5f, (double)(tid - SL)));
    }
    __syncthreads();

    const int base = blockIdx.x * P;
    int pi = base + lane;
    if (pi >= B) pi = B - 1;
    const float4 c = __ldg(&coords[pi]);

#pragma unroll 1
    for (int i = 0; i < 7; i++) {
        int s = w + i * 8;
        if (s < SL) {
            float r = ress[s];
            float x = c.x * r, y = c.y * r, z = c.z * r;
            float fx = floorf(x), fy = floorf(y), fz = floorf(z);
            float wx = x - fx, wy = y - fy, wz = z - fz;
            float mx = 1.f - wx, my = 1.f - wy, mz = 1.f - wz;
            unsigned ux = (unsigned)fx, uy = (unsigned)fy, uz = (unsigned)fz;
            unsigned hx0 = ux, hx1 = ux + 1u;
            unsigned hy0 = uy * 2654435761u, hy1 = (uy + 1u) * 2654435761u;
            unsigned hz0 = uz * 805459861u,  hz1 = (uz + 1u) * 805459861u;
            float mymz = my * mz, wymz = wy * mz, mywz = my * wz, wywz = wy * wz;
            const float2* tb = stab + (size_t)s * SENT;
            // issue all 8 loads, then combine
            ull f0 = *(const ull*)(tb + (((hx0 ^ hy0 ^ hz0) & SMASK)));
            ull f1 = *(const ull*)(tb + (((hx1 ^ hy0 ^ hz0) & SMASK)));
            ull f2 = *(const ull*)(tb + (((hx0 ^ hy1 ^ hz0) & SMASK)));
            ull f3 = *(const ull*)(tb + (((hx1 ^ hy1 ^ hz0) & SMASK)));
            ull f4 = *(const ull*)(tb + (((hx0 ^ hy0 ^ hz1) & SMASK)));
            ull f5 = *(const ull*)(tb + (((hx1 ^ hy0 ^ hz1) & SMASK)));
            ull f6 = *(const ull*)(tb + (((hx0 ^ hy1 ^ hz1) & SMASK)));
            ull f7 = *(const ull*)(tb + (((hx1 ^ hy1 ^ hz1) & SMASK)));
            ull acc = mul2(f0, splat2(mx * mymz));
            acc = fma2(f1, splat2(wx * mymz), acc);
            acc = fma2(f2, splat2(mx * wymz), acc);
            acc = fma2(f3, splat2(wx * wymz), acc);
            acc = fma2(f4, splat2(mx * mywz), acc);
            acc = fma2(f5, splat2(wx * mywz), acc);
            acc = fma2(f6, splat2(mx * wywz), acc);
            acc = fma2(f7, splat2(wx * wywz), acc);
            float2 a = unpack2(acc);
            __stcs(&g_feats[(size_t)(2 * s) * MAXB + pi],     a.x);
            __stcs(&g_feats[(size_t)(2 * s + 1) * MAXB + pi], a.y);
        } else {
            int l = s - SL;
            float r  = ress[s];
            float tx = c.w * r;
            float tf = floorf(tx);
            float tw = tx - tf;
            unsigned t0 = (unsigned)tf;
            const float2* tb = ttab + (size_t)l * TENT;
            ull f0 = *(const ull*)(tb + (t0 & TMASK));
            ull f1 = *(const ull*)(tb + ((t0 + 1u) & TMASK));
            ull acc = mul2(f0, splat2(1.f - tw));
            acc = fma2(f1, splat2(tw), acc);
            float2 a = unpack2(acc);
            __stcs(&g_feats[(size_t)(2 * SL + 2 * l) * MAXB + pi],     a.x);
            __stcs(&g_feats[(size_t)(2 * SL + 2 * l + 1) * MAXB + pi], a.y);
        }
    }
}

// ============================================================================
// Kernel 2: MLP. 128 threads, 32 points/block. Thread tile 4j x 8p.
// Layer 1 reads k-major global features; layer 2 reads h1 from smem.
// ============================================================================
template <int K, bool GLOBAL_IN, bool WRITE>
__device__ __forceinline__ void mlp_layer(const float* __restrict__ W,
                                          const float* __restrict__ bias,
                                          const float* __restrict__ g,
                                          const float* __restrict__ beta,
                                          const float* __restrict__ in,  // global base (+base+p0 offset applied)
                                          float* buf, float* red,
                                          int j0, int p0, int w, int tj,
                                          float outn[4][8])
{
    ull acc[4][4];
#pragma unroll
    for (int a = 0; a < 4; a++)
#pragma unroll
        for (int q = 0; q < 4; q++) acc[a][q] = 0ull;

#pragma unroll 4
    for (int k = 0; k < K; k++) {
        float4 wv = __ldg((const float4*)(W + k * HID + j0));
        float4 fA, fB;
        if (GLOBAL_IN) {
            const float4* fr = (const float4*)(in + (size_t)k * MAXB);
            fA = __ldg(&fr[0]);
            fB = __ldg(&fr[1]);
        } else {
            const float4* fr = (const float4*)(buf + k * RS + p0);
            fA = fr[0];
            fB = fr[1];
        }
        ull q0 = pack2(fA.x, fA.y), q1 = pack2(fA.z, fA.w);
        ull q2 = pack2(fB.x, fB.y), q3 = pack2(fB.z, fB.w);
        ull s;
        s = splat2(wv.x);
        acc[0][0] = fma2(q0, s, acc[0][0]); acc[0][1] = fma2(q1, s, acc[0][1]);
        acc[0][2] = fma2(q2, s, acc[0][2]); acc[0][3] = fma2(q3, s, acc[0][3]);
        s = splat2(wv.y);
        acc[1][0] = fma2(q0, s, acc[1][0]); acc[1][1] = fma2(q1, s, acc[1][1]);
        acc[1][2] = fma2(q2, s, acc[1][2]); acc[1][3] = fma2(q3, s, acc[1][3]);
        s = splat2(wv.z);
        acc[2][0] = fma2(q0, s, acc[2][0]); acc[2][1] = fma2(q1, s, acc[2][1]);
        acc[2][2] = fma2(q2, s, acc[2][2]); acc[2][3] = fma2(q3, s, acc[2][3]);
        s = splat2(wv.w);
        acc[3][0] = fma2(q0, s, acc[3][0]); acc[3][1] = fma2(q1, s, acc[3][1]);
        acc[3][2] = fma2(q2, s, acc[3][2]); acc[3][3] = fma2(q3, s, acc[3][3]);
    }

    float4 bv = __ldg((const float4*)(bias + j0));
    float bb[4] = {bv.x, bv.y, bv.z, bv.w};
    float s1[8], s2[8];
#pragma unroll
    for (int p = 0; p < 8; p++) { s1[p] = 0.f; s2[p] = 0.f; }
#pragma unroll
    for (int a = 0; a < 4; a++) {
#pragma unroll
        for (int q = 0; q < 4; q++) {
            float2 vv = unpack2(acc[a][q]);
            float v0 = fmaxf(vv.x + bb[a], 0.f);
            float v1 = fmaxf(vv.y + bb[a], 0.f);
            outn[a][2 * q]     = v0;
            outn[a][2 * q + 1] = v1;
            s1[2 * q]     += v0; s2[2 * q]     += v0 * v0;
            s1[2 * q + 1] += v1; s2[2 * q + 1] += v1 * v1;
        }
    }
#pragma unroll
    for (int o = 1; o < 8; o <<= 1) {
#pragma unroll
        for (int p = 0; p < 8; p++) {
            s1[p] += __shfl_xor_sync(0xffffffffu, s1[p], o);
            s2[p] += __shfl_xor_sync(0xffffffffu, s2[p], o);
        }
    }
    if (tj == 0) {
#pragma unroll
        for (int p = 0; p < 8; p++) {
            red[(0 * P + p0 + p) * 4 + w] = s1[p];
            red[(1 * P + p0 + p) * 4 + w] = s2[p];
        }
    }
    __syncthreads();

    float4 gv  = __ldg((const float4*)(g + j0));
    float4 btv = __ldg((const float4*)(beta + j0));
    float gg[4] = {gv.x, gv.y, gv.z, gv.w};
    float bt[4] = {btv.x, btv.y, btv.z, btv.w};
#pragma unroll
    for (int p = 0; p < 8; p++) {
        const float* r0 = &red[(0 * P + p0 + p) * 4];
        const float* r1 = &red[(1 * P + p0 + p) * 4];
        float S1 = (r0[0] + r0[1]) + (r0[2] + r0[3]);
        float S2 = (r1[0] + r1[1]) + (r1[2] + r1[3]);
        float m   = S1 * (1.f / HID);
        float var = S2 * (1.f / HID) - m * m;
        float rs  = rsqrtf(var + 1e-5f);
#pragma unroll
        for (int a = 0; a < 4; a++)
            outn[a][p] = (outn[a][p] - m) * rs * gg[a] + bt[a];
    }
    if (WRITE) {
#pragma unroll
        for (int a = 0; a < 4; a++) {
            float* row = buf + (j0 + a) * RS + p0;
            ((float4*)row)[0] = make_float4(outn[a][0], outn[a][1], outn[a][2], outn[a][3]);
            ((float4*)row)[1] = make_float4(outn[a][4], outn[a][5], outn[a][6], outn[a][7]);
        }
    }
    __syncthreads();
}

__global__ __launch_bounds__(NT)
void mlp_kernel(const float*  __restrict__ w1,
                const float*  __restrict__ b1,
                const float*  __restrict__ g1,
                const float*  __restrict__ beta1,
                const float*  __restrict__ w2,
                const float*  __restrict__ b2,
                const float*  __restrict__ g2,
                const float*  __restrict__ beta2,
                const float*  __restrict__ w3,
                const float*  __restrict__ b3,
                float* __restrict__ out, int B)
{
    __shared__ __align__(16) float buf[HID * RS];
    __shared__ float red[2 * P * 4];
    __shared__ float red3[4 * P];

    const int tid  = threadIdx.x;
    const int w    = tid >> 5;
    const int lane = tid & 31;
    const int tj = lane & 7;
    const int tp = lane >> 3;
    const int j0 = w * 32 + tj * 4;
    const int p0 = tp * 8;
    const int base = blockIdx.x * P;

    float h[4][8];
    mlp_layer<ENC, true,  true >(w1, b1, g1, beta1, g_feats + base + p0, buf, red, j0, p0, w, tj, h);
    mlp_layer<HID, false, false>(w2, b2, g2, beta2, nullptr,             buf, red, j0, p0, w, tj, h);

    {
        float4 w3v = __ldg((const float4*)(w3 + j0));
        float part[8];
#pragma unroll
        for (int p = 0; p < 8; p++)
            part[p] = h[0][p] * w3v.x + h[1][p] * w3v.y
                    + h[2][p] * w3v.z + h[3][p] * w3v.w;
#pragma unroll
        for (int o = 1; o < 8; o <<= 1)
#pragma unroll
            for (int p = 0; p < 8; p++)
                part[p] += __shfl_xor_sync(0xffffffffu, part[p], o);
        if (tj == 0) {
#pragma unroll
            for (int p = 0; p < 8; p++)
                red3[w * P + p0 + p] = part[p];
        }
        __syncthreads();
        if (tid < P) {
            float o = red3[0 * P + tid] + red3[1 * P + tid]
                    + red3[2 * P + tid] + red3[3 * P + tid] + __ldg(&b3[0]);
            int po = base + tid;
            if (po < B) out[po] = o;
        }
    }
}

extern "C" void kernel_launch(void* const* d_in, const int* in_sizes, int n_in,
                              void* d_out, int out_size) {
    const float4* coords = (const float4*)d_in[0];
    const float2* stab   = (const float2*)d_in[1];
    const float2* ttab   = (const float2*)d_in[2];
    const float*  w1     = (const float*)d_in[3];
    const float*  b1     = (const float*)d_in[4];
    const float*  g1     = (const float*)d_in[5];
    const float*  be1    = (const float*)d_in[6];
    const float*  w2     = (const float*)d_in[7];
    const float*  b2     = (const float*)d_in[8];
    const float*  g2     = (const float*)d_in[9];
    const float*  be2    = (const float*)d_in[10];
    const float*  w3     = (const float*)d_in[11];
    const float*  b3     = (const float*)d_in[12];
    float* out = (float*)d_out;

    int B = in_sizes[0] / 4;
    if (B > MAXB) B = MAXB;
    int blocks = (B + P - 1) / P;

    encode_kernel<<<blocks, 256>>>(coords, stab, ttab, B);
    mlp_kernel<<<blocks, NT>>>(w1, b1, g1, be1, w2, b2, g2, be2, w3, b3, out, B);
}

// round 4
// speedup vs baseline: 1.1898x; 1.1898x over previous
#include <cuda_runtime.h>
#include <math.h>

typedef unsigned long long ull;

#define SL 36
#define TL 20
#define SENT (1u << 19)
#define TENT (1u << 17)
#define SMASK (SENT - 1u)
#define TMASK (TENT - 1u)
#define HID 128
#define ENC 112
#define NSLOT (SL + TL)   // 56
#define P 32              // points per MLP block
#define NT 128            // threads per MLP block
#define RS 36             // smem row stride (floats)
#define MAXB 131072

// global scratch: features, k-major [ENC][MAXB]
__device__ __align__(16) float g_feats[ENC * MAXB];

// ---- packed fp32x2 helpers (sm_103a FFMA2 path) -----------------------------
__device__ __forceinline__ ull splat2(float v) {
    ull r; asm("mov.b64 %0, {%1, %1};" : "=l"(r) : "f"(v)); return r;
}
__device__ __forceinline__ ull pack2(float a, float b) {
    ull r; asm("mov.b64 %0, {%1, %2};" : "=l"(r) : "f"(a), "f"(b)); return r;
}
__device__ __forceinline__ float2 unpack2(ull v) {
    float2 r; asm("mov.b64 {%0, %1}, %2;" : "=f"(r.x), "=f"(r.y) : "l"(v)); return r;
}
__device__ __forceinline__ ull fma2(ull a, ull b, ull c) {
    ull d; asm("fma.rn.f32x2 %0, %1, %2, %3;" : "=l"(d) : "l"(a), "l"(b), "l"(c)); return d;
}
__device__ __forceinline__ ull mul2(ull a, ull b) {
    ull d; asm("mul.rn.f32x2 %0, %1, %2;" : "=l"(d) : "l"(a), "l"(b)); return d;
}

// ============================================================================
// Kernel 1: hash-grid encode. 256 threads, 32 points/block, lane = point,
// warp-uniform level s = w + 8*i. Output streamed to g_feats (k-major).
// ============================================================================
__global__ __launch_bounds__(256)
void encode_kernel(const float4* __restrict__ coords,
                   const float2* __restrict__ stab,
                   const float2* __restrict__ ttab,
                   int B)
{
    __shared__ float ress[NSLOT];
    const int tid  = threadIdx.x;
    const int w    = tid >> 5;
    const int lane = tid & 31;

    if (tid < SL) {
        ress[tid] = floorf(16.0f * (float)pow((double)1.38f, (double)tid));
    } else if (tid < NSLOT) {
        ress[tid] = floorf(16.0f * (float)pow((double)1.5f, (double)(tid - SL)));
    }
    __syncthreads();

    const int base = blockIdx.x * P;
    int pi = base + lane;
    if (pi >= B) pi = B - 1;
    const float4 c = __ldg(&coords[pi]);

#pragma unroll 1
    for (int i = 0; i < 7; i++) {
        int s = w + i * 8;
        if (s < SL) {
            float r = ress[s];
            float x = c.x * r, y = c.y * r, z = c.z * r;
            float fx = floorf(x), fy = floorf(y), fz = floorf(z);
            float wx = x - fx, wy = y - fy, wz = z - fz;
            float mx = 1.f - wx, my = 1.f - wy, mz = 1.f - wz;
            unsigned ux = (unsigned)fx, uy = (unsigned)fy, uz = (unsigned)fz;
            unsigned hx0 = ux, hx1 = ux + 1u;
            unsigned hy0 = uy * 2654435761u, hy1 = (uy + 1u) * 2654435761u;
            unsigned hz0 = uz * 805459861u,  hz1 = (uz + 1u) * 805459861u;
            float mymz = my * mz, wymz = wy * mz, mywz = my * wz, wywz = wy * wz;
            const float2* tb = stab + (size_t)s * SENT;
            ull f0 = *(const ull*)(tb + (((hx0 ^ hy0 ^ hz0) & SMASK)));
            ull f1 = *(const ull*)(tb + (((hx1 ^ hy0 ^ hz0) & SMASK)));
            ull f2 = *(const ull*)(tb + (((hx0 ^ hy1 ^ hz0) & SMASK)));
            ull f3 = *(const ull*)(tb + (((hx1 ^ hy1 ^ hz0) & SMASK)));
            ull f4 = *(const ull*)(tb + (((hx0 ^ hy0 ^ hz1) & SMASK)));
            ull f5 = *(const ull*)(tb + (((hx1 ^ hy0 ^ hz1) & SMASK)));
            ull f6 = *(const ull*)(tb + (((hx0 ^ hy1 ^ hz1) & SMASK)));
            ull f7 = *(const ull*)(tb + (((hx1 ^ hy1 ^ hz1) & SMASK)));
            ull acc = mul2(f0, splat2(mx * mymz));
            acc = fma2(f1, splat2(wx * mymz), acc);
            acc = fma2(f2, splat2(mx * wymz), acc);
            acc = fma2(f3, splat2(wx * wymz), acc);
            acc = fma2(f4, splat2(mx * mywz), acc);
            acc = fma2(f5, splat2(wx * mywz), acc);
            acc = fma2(f6, splat2(mx * wywz), acc);
            acc = fma2(f7, splat2(wx * wywz), acc);
            float2 a = unpack2(acc);
            __stcs(&g_feats[(size_t)(2 * s) * MAXB + pi],     a.x);
            __stcs(&g_feats[(size_t)(2 * s + 1) * MAXB + pi], a.y);
        } else {
            int l = s - SL;
            float r  = ress[s];
            float tx = c.w * r;
            float tf = floorf(tx);
            float tw = tx - tf;
            unsigned t0 = (unsigned)tf;
            const float2* tb = ttab + (size_t)l * TENT;
            ull f0 = *(const ull*)(tb + (t0 & TMASK));
            ull f1 = *(const ull*)(tb + ((t0 + 1u) & TMASK));
            ull acc = mul2(f0, splat2(1.f - tw));
            acc = fma2(f1, splat2(tw), acc);
            float2 a = unpack2(acc);
            __stcs(&g_feats[(size_t)(2 * SL + 2 * l) * MAXB + pi],     a.x);
            __stcs(&g_feats[(size_t)(2 * SL + 2 * l + 1) * MAXB + pi], a.y);
        }
    }
}

// ============================================================================
// Kernel 2: MLP. 128 threads, 32 points/block. Thread tile 4j x 8p.
// Both layers read activations from smem (layer-1 tile staged coalesced).
// ============================================================================
template <int K, bool WRITE>
__device__ __forceinline__ void mlp_layer(const float* __restrict__ W,
                                          const float* __restrict__ bias,
                                          const float* __restrict__ g,
                                          const float* __restrict__ beta,
                                          float* buf, float* red,
                                          int j0, int p0, int w, int tj,
                                          float outn[4][8])
{
    ull acc[4][4];
#pragma unroll
    for (int a = 0; a < 4; a++)
#pragma unroll
        for (int q = 0; q < 4; q++) acc[a][q] = 0ull;

#pragma unroll 4
    for (int k = 0; k < K; k++) {
        float4 wv = __ldg((const float4*)(W + k * HID + j0));
        const float4* fr = (const float4*)(buf + k * RS + p0);
        float4 fA = fr[0];
        float4 fB = fr[1];
        ull q0 = pack2(fA.x, fA.y), q1 = pack2(fA.z, fA.w);
        ull q2 = pack2(fB.x, fB.y), q3 = pack2(fB.z, fB.w);
        ull s;
        s = splat2(wv.x);
        acc[0][0] = fma2(q0, s, acc[0][0]); acc[0][1] = fma2(q1, s, acc[0][1]);
        acc[0][2] = fma2(q2, s, acc[0][2]); acc[0][3] = fma2(q3, s, acc[0][3]);
        s = splat2(wv.y);
        acc[1][0] = fma2(q0, s, acc[1][0]); acc[1][1] = fma2(q1, s, acc[1][1]);
        acc[1][2] = fma2(q2, s, acc[1][2]); acc[1][3] = fma2(q3, s, acc[1][3]);
        s = splat2(wv.z);
        acc[2][0] = fma2(q0, s, acc[2][0]); acc[2][1] = fma2(q1, s, acc[2][1]);
        acc[2][2] = fma2(q2, s, acc[2][2]); acc[2][3] = fma2(q3, s, acc[2][3]);
        s = splat2(wv.w);
        acc[3][0] = fma2(q0, s, acc[3][0]); acc[3][1] = fma2(q1, s, acc[3][1]);
        acc[3][2] = fma2(q2, s, acc[3][2]); acc[3][3] = fma2(q3, s, acc[3][3]);
    }

    float4 bv = __ldg((const float4*)(bias + j0));
    float bb[4] = {bv.x, bv.y, bv.z, bv.w};
    float s1[8], s2[8];
#pragma unroll
    for (int p = 0; p < 8; p++) { s1[p] = 0.f; s2[p] = 0.f; }
#pragma unroll
    for (int a = 0; a < 4; a++) {
#pragma unroll
        for (int q = 0; q < 4; q++) {
            float2 vv = unpack2(acc[a][q]);
            float v0 = fmaxf(vv.x + bb[a], 0.f);
            float v1 = fmaxf(vv.y + bb[a], 0.f);
            outn[a][2 * q]     = v0;
            outn[a][2 * q + 1] = v1;
            s1[2 * q]     += v0; s2[2 * q]     += v0 * v0;
            s1[2 * q + 1] += v1; s2[2 * q + 1] += v1 * v1;
        }
    }
#pragma unroll
    for (int o = 1; o < 8; o <<= 1) {
#pragma unroll
        for (int p = 0; p < 8; p++) {
            s1[p] += __shfl_xor_sync(0xffffffffu, s1[p], o);
            s2[p] += __shfl_xor_sync(0xffffffffu, s2[p], o);
        }
    }
    if (tj == 0) {
#pragma unroll
        for (int p = 0; p < 8; p++) {
            red[(0 * P + p0 + p) * 4 + w] = s1[p];
            red[(1 * P + p0 + p) * 4 + w] = s2[p];
        }
    }
    __syncthreads();

    float4 gv  = __ldg((const float4*)(g + j0));
    float4 btv = __ldg((const float4*)(beta + j0));
    float gg[4] = {gv.x, gv.y, gv.z, gv.w};
    float bt[4] = {btv.x, btv.y, btv.z, btv.w};
#pragma unroll
    for (int p = 0; p < 8; p++) {
        const float* r0 = &red[(0 * P + p0 + p) * 4];
        const float* r1 = &red[(1 * P + p0 + p) * 4];
        float S1 = (r0[0] + r0[1]) + (r0[2] + r0[3]);
        float S2 = (r1[0] + r1[1]) + (r1[2] + r1[3]);
        float m   = S1 * (1.f / HID);
        float var = S2 * (1.f / HID) - m * m;
        float rs  = rsqrtf(var + 1e-5f);
#pragma unroll
        for (int a = 0; a < 4; a++)
            outn[a][p] = (outn[a][p] - m) * rs * gg[a] + bt[a];
    }
    if (WRITE) {
#pragma unroll
        for (int a = 0; a < 4; a++) {
            float* row = buf + (j0 + a) * RS + p0;
            ((float4*)row)[0] = make_float4(outn[a][0], outn[a][1], outn[a][2], outn[a][3]);
            ((float4*)row)[1] = make_float4(outn[a][4], outn[a][5], outn[a][6], outn[a][7]);
        }
    }
    __syncthreads();
}

__global__ __launch_bounds__(NT, 8)
void mlp_kernel(const float*  __restrict__ w1,
                const float*  __restrict__ b1,
                const float*  __restrict__ g1,
                const float*  __restrict__ beta1,
                const float*  __restrict__ w2,
                const float*  __restrict__ b2,
                const float*  __restrict__ g2,
                const float*  __restrict__ beta2,
                const float*  __restrict__ w3,
                const float*  __restrict__ b3,
                float* __restrict__ out, int B)
{
    __shared__ __align__(16) float buf[HID * RS];
    __shared__ float red[2 * P * 4];
    __shared__ float red3[4 * P];

    const int tid  = threadIdx.x;
    const int w    = tid >> 5;
    const int lane = tid & 31;
    const int tj = lane & 7;
    const int tp = lane >> 3;
    const int j0 = w * 32 + tj * 4;
    const int p0 = tp * 8;
    const int base = blockIdx.x * P;

    // ---- stage feature tile [ENC][32] into smem (coalesced, streaming) ----
#pragma unroll
    for (int it = 0; it < ENC * 8 / NT; it++) {
        int idx = it * NT + tid;          // 0 .. 895
        int k = idx >> 3;
        int q = idx & 7;
        float4 v = __ldcs((const float4*)(g_feats + (size_t)k * MAXB + base) + q);
        *(float4*)(buf + k * RS + 4 * q) = v;
    }
    __syncthreads();

    float h[4][8];
    mlp_layer<ENC, true >(w1, b1, g1, beta1, buf, red, j0, p0, w, tj, h);
    mlp_layer<HID, false>(w2, b2, g2, beta2, buf, red, j0, p0, w, tj, h);

    {
        float4 w3v = __ldg((const float4*)(w3 + j0));
        float part[8];
#pragma unroll
        for (int p = 0; p < 8; p++)
            part[p] = h[0][p] * w3v.x + h[1][p] * w3v.y
                    + h[2][p] * w3v.z + h[3][p] * w3v.w;
#pragma unroll
        for (int o = 1; o < 8; o <<= 1)
#pragma unroll
            for (int p = 0; p < 8; p++)
                part[p] += __shfl_xor_sync(0xffffffffu, part[p], o);
        if (tj == 0) {
#pragma unroll
            for (int p = 0; p < 8; p++)
                red3[w * P + p0 + p] = part[p];
        }
        __syncthreads();
        if (tid < P) {
            float o = red3[0 * P + tid] + red3[1 * P + tid]
                    + red3[2 * P + tid] + red3[3 * P + tid] + __ldg(&b3[0]);
            int po = base + tid;
            if (po < B) out[po] = o;
        }
    }
}

extern "C" void kernel_launch(void* const* d_in, const int* in_sizes, int n_in,
                              void* d_out, int out_size) {
    const float4* coords = (const float4*)d_in[0];
    const float2* stab   = (const float2*)d_in[1];
    const float2* ttab   = (const float2*)d_in[2];
    const float*  w1     = (const float*)d_in[3];
    const float*  b1     = (const float*)d_in[4];
    const float*  g1     = (const float*)d_in[5];
    const float*  be1    = (const float*)d_in[6];
    const float*  w2     = (const float*)d_in[7];
    const float*  b2     = (const float*)d_in[8];
    const float*  g2     = (const float*)d_in[9];
    const float*  be2    = (const float*)d_in[10];
    const float*  w3     = (const float*)d_in[11];
    const float*  b3     = (const float*)d_in[12];
    float* out = (float*)d_out;

    int B = in_sizes[0] / 4;
    if (B > MAXB) B = MAXB;
    int blocks = (B + P - 1) / P;

    encode_kernel<<<blocks, 256>>>(coords, stab, ttab, B);
    mlp_kernel<<<blocks, NT>>>(w1, b1, g1, be1, w2, b2, g2, be2, w3, b3, out, B);
}

// round 6
// speedup vs baseline: 1.4134x; 1.1879x over previous
#include <cuda_runtime.h>
#include <cuda_bf16.h>
#include <math.h>

typedef unsigned long long ull;
typedef unsigned int u32;

#define SL 36
#define TL 20
#define SENT (1u << 19)
#define TENT (1u << 17)
#define SMASK (SENT - 1u)
#define TMASK (TENT - 1u)
#define HID 128
#define ENC 112
#define NSLOT (SL + TL)
#define P 32
#define MAXB 131072
#define VROW 132

// k-major features [ENC][MAXB]
__device__ __align__(16) float g_feats[ENC * MAXB];
// weights pre-arranged in mma fragment order:
// [w(4)][kt(8)][lane(32)][mt(2) x areg(4)] u32 (bf16 pairs)
__device__ __align__(16) u32 g_w1hi[4 * 8 * 32 * 8];
__device__ __align__(16) u32 g_w1lo[4 * 8 * 32 * 8];
__device__ __align__(16) u32 g_w2hi[4 * 8 * 32 * 8];
__device__ __align__(16) u32 g_w2lo[4 * 8 * 32 * 8];

// ---- fp32x2 helpers (encode kernel) ----------------------------------------
__device__ __forceinline__ ull splat2(float v) {
    ull r; asm("mov.b64 %0, {%1, %1};" : "=l"(r) : "f"(v)); return r;
}
__device__ __forceinline__ float2 unpack2(ull v) {
    float2 r; asm("mov.b64 {%0, %1}, %2;" : "=f"(r.x), "=f"(r.y) : "l"(v)); return r;
}
__device__ __forceinline__ ull fma2(ull a, ull b, ull c) {
    ull d; asm("fma.rn.f32x2 %0, %1, %2, %3;" : "=l"(d) : "l"(a), "l"(b), "l"(c)); return d;
}
__device__ __forceinline__ ull mul2(ull a, ull b) {
    ull d; asm("mul.rn.f32x2 %0, %1, %2;" : "=l"(d) : "l"(a), "l"(b)); return d;
}

// ---- bf16 split / mma helpers ----------------------------------------------
__device__ __forceinline__ void split2(float x0, float x1, u32& hp, u32& lp) {
    __nv_bfloat16 h0 = __float2bfloat16(x0);
    __nv_bfloat16 h1 = __float2bfloat16(x1);
    __nv_bfloat16 l0 = __float2bfloat16(x0 - __bfloat162float(h0));
    __nv_bfloat16 l1 = __float2bfloat16(x1 - __bfloat162float(h1));
    hp = ((u32)__bfloat16_as_ushort(h1) << 16) | __bfloat16_as_ushort(h0);
    lp = ((u32)__bfloat16_as_ushort(l1) << 16) | __bfloat16_as_ushort(l0);
}

__device__ __forceinline__ void mma16816(float* d, u32 a0, u32 a1, u32 a2, u32 a3,
                                         u32 b0, u32 b1) {
    asm volatile(
        "mma.sync.aligned.m16n8k16.row.col.f32.bf16.bf16.f32 "
        "{%0,%1,%2,%3}, {%4,%5,%6,%7}, {%8,%9}, {%0,%1,%2,%3};"
        : "+f"(d[0]), "+f"(d[1]), "+f"(d[2]), "+f"(d[3])
        : "r"(a0), "r"(a1), "r"(a2), "r"(a3), "r"(b0), "r"(b1));
}

// bfrag index: [kt][nt][reg][lane]
__device__ __forceinline__ int bidx(int kt, int nt, int reg, int lane) {
    return ((kt * 4 + nt) * 2 + reg) * 32 + lane;
}

// ============================================================================
// setup kernel: weights -> bf16 hi/lo in fragment order. 32768 threads.
// t bits: r=t&7 (mt*4+areg), lane=(t>>3)&31, kt=(t>>8)&7, w=(t>>11)&3,
//         half=(t>>13)&1 (0=hi), layer=(t>>14)&1
// ============================================================================
__global__ void setup_kernel(const float* __restrict__ w1, const float* __restrict__ w2) {
    int t = blockIdx.x * blockDim.x + threadIdx.x;
    int r     = t & 7;
    int lane  = (t >> 3) & 31;
    int kt    = (t >> 8) & 7;
    int w     = (t >> 11) & 3;
    int half  = (t >> 13) & 1;
    int layer = (t >> 14) & 1;
    int g  = lane >> 2;
    int tg = lane & 3;
    int mt = r >> 2;
    int rr = r & 3;
    int j  = w * 32 + mt * 16 + g + ((rr & 1) ? 8 : 0);
    int k0 = kt * 16 + tg * 2 + ((rr >> 1) ? 8 : 0);
    int k1 = k0 + 1;
    const float* W = layer ? w2 : w1;
    float x0 = (layer || k0 < ENC) ? W[k0 * HID + j] : 0.f;
    float x1 = (layer || k1 < ENC) ? W[k1 * HID + j] : 0.f;
    u32 hp, lp;
    split2(x0, x1, hp, lp);
    int idx = ((w * 8 + kt) * 32 + lane) * 8 + r;
    u32 val = half ? lp : hp;
    if (layer == 0) { if (half) g_w1lo[idx] = val; else g_w1hi[idx] = val; }
    else            { if (half) g_w2lo[idx] = val; else g_w2hi[idx] = val; }
}

// ============================================================================
// encode kernel (unchanged from round 4 — near its gather-wavefront floor)
// ============================================================================
__global__ __launch_bounds__(256)
void encode_kernel(const float4* __restrict__ coords,
                   const float2* __restrict__ stab,
                   const float2* __restrict__ ttab,
                   int B)
{
    __shared__ float ress[NSLOT];
    const int tid  = threadIdx.x;
    const int w    = tid >> 5;
    const int lane = tid & 31;

    if (tid < SL) {
        ress[tid] = floorf(16.0f * (float)pow((double)1.38f, (double)tid));
    } else if (tid < NSLOT) {
        ress[tid] = floorf(16.0f * (float)pow((double)1.5f, (double)(tid - SL)));
    }
    __syncthreads();

    const int base = blockIdx.x * P;
    int pi = base + lane;
    if (pi >= B) pi = B - 1;
    const float4 c = __ldg(&coords[pi]);

#pragma unroll 1
    for (int i = 0; i < 7; i++) {
        int s = w + i * 8;
        if (s < SL) {
            float r = ress[s];
            float x = c.x * r, y = c.y * r, z = c.z * r;
            float fx = floorf(x), fy = floorf(y), fz = floorf(z);
            float wx = x - fx, wy = y - fy, wz = z - fz;
            float mx = 1.f - wx, my = 1.f - wy, mz = 1.f - wz;
            unsigned ux = (unsigned)fx, uy = (unsigned)fy, uz = (unsigned)fz;
            unsigned hx0 = ux, hx1 = ux + 1u;
            unsigned hy0 = uy * 2654435761u, hy1 = (uy + 1u) * 2654435761u;
            unsigned hz0 = uz * 805459861u,  hz1 = (uz + 1u) * 805459861u;
            float mymz = my * mz, wymz = wy * mz, mywz = my * wz, wywz = wy * wz;
            const float2* tb = stab + (size_t)s * SENT;
            ull f0 = *(const ull*)(tb + (((hx0 ^ hy0 ^ hz0) & SMASK)));
            ull f1 = *(const ull*)(tb + (((hx1 ^ hy0 ^ hz0) & SMASK)));
            ull f2 = *(const ull*)(tb + (((hx0 ^ hy1 ^ hz0) & SMASK)));
            ull f3 = *(const ull*)(tb + (((hx1 ^ hy1 ^ hz0) & SMASK)));
            ull f4 = *(const ull*)(tb + (((hx0 ^ hy0 ^ hz1) & SMASK)));
            ull f5 = *(const ull*)(tb + (((hx1 ^ hy0 ^ hz1) & SMASK)));
            ull f6 = *(const ull*)(tb + (((hx0 ^ hy1 ^ hz1) & SMASK)));
            ull f7 = *(const ull*)(tb + (((hx1 ^ hy1 ^ hz1) & SMASK)));
            ull acc = mul2(f0, splat2(mx * mymz));
            acc = fma2(f1, splat2(wx * mymz), acc);
            acc = fma2(f2, splat2(mx * wymz), acc);
            acc = fma2(f3, splat2(wx * wymz), acc);
            acc = fma2(f4, splat2(mx * mywz), acc);
            acc = fma2(f5, splat2(wx * mywz), acc);
            acc = fma2(f6, splat2(mx * wywz), acc);
            acc = fma2(f7, splat2(wx * wywz), acc);
            float2 a = unpack2(acc);
            __stcs(&g_feats[(size_t)(2 * s) * MAXB + pi],     a.x);
            __stcs(&g_feats[(size_t)(2 * s + 1) * MAXB + pi], a.y);
        } else {
            int l = s - SL;
            float r  = ress[s];
            float tx = c.w * r;
            float tf = floorf(tx);
            float tw = tx - tf;
            unsigned t0 = (unsigned)tf;
            const float2* tb = ttab + (size_t)l * TENT;
            ull f0 = *(const ull*)(tb + (t0 & TMASK));
            ull f1 = *(const ull*)(tb + ((t0 + 1u) & TMASK));
            ull acc = mul2(f0, splat2(1.f - tw));
            acc = fma2(f1, splat2(tw), acc);
            float2 a = unpack2(acc);
            __stcs(&g_feats[(size_t)(2 * SL + 2 * l) * MAXB + pi],     a.x);
            __stcs(&g_feats[(size_t)(2 * SL + 2 * l + 1) * MAXB + pi], a.y);
        }
    }
}

// ============================================================================
// MLP kernel: mma.sync m16n8k16 bf16, 3-term split. 128 threads, 32 pts/block.
// Warp w owns j rows [w*32, w*32+32). D tile per warp: 32j x 32p.
// ============================================================================
__global__ __launch_bounds__(128)
void mlp_mma_kernel(const float* __restrict__ b1, const float* __restrict__ g1,
                    const float* __restrict__ bt1,
                    const float* __restrict__ b2, const float* __restrict__ g2,
                    const float* __restrict__ bt2,
                    const float* __restrict__ w3, const float* __restrict__ b3,
                    float* __restrict__ out, int B)
{
    __shared__ u32 bhi[2048];
    __shared__ u32 blo[2048];
    __shared__ __align__(16) float vmat[32 * VROW];

    const int tid  = threadIdx.x;
    const int w    = tid >> 5;
    const int lane = tid & 31;
    const int g    = lane >> 2;
    const int tg   = lane & 3;
    const int base = blockIdx.x * P;

    // ---- stage features -> bfrag (bf16 hi/lo, fragment-linear layout) ------
#pragma unroll
    for (int it = 0; it < 4; it++) {
        int task = it * 128 + tid;     // 0..511
        int kp = task >> 3;            // k-pair 0..63
        int q  = task & 7;             // point group of 4
        float4 f0 = make_float4(0.f, 0.f, 0.f, 0.f);
        float4 f1 = f0;
        if (kp < ENC / 2) {
            f0 = __ldcs(((const float4*)(g_feats + (size_t)(2 * kp)     * MAXB + base)) + q);
            f1 = __ldcs(((const float4*)(g_feats + (size_t)(2 * kp + 1) * MAXB + base)) + q);
        }
        int kt = kp >> 3, qq = kp & 7, reg = qq >> 2, tgq = qq & 3;
        float x0s[4] = {f0.x, f0.y, f0.z, f0.w};
        float x1s[4] = {f1.x, f1.y, f1.z, f1.w};
#pragma unroll
        for (int e = 0; e < 4; e++) {
            int p = q * 4 + e;
            u32 hp, lp;
            split2(x0s[e], x1s[e], hp, lp);
            int idx = bidx(kt, p >> 3, reg, (p & 7) * 4 + tgq);
            bhi[idx] = hp;
            blo[idx] = lp;
        }
    }
    __syncthreads();

#pragma unroll 1
    for (int layer = 0; layer < 2; layer++) {
        const u32* WH = layer ? g_w2hi : g_w1hi;
        const u32* WL = layer ? g_w2lo : g_w1lo;

        float d[2][4][4];
#pragma unroll
        for (int mt = 0; mt < 2; mt++)
#pragma unroll
            for (int nt = 0; nt < 4; nt++)
#pragma unroll
                for (int e = 0; e < 4; e++) d[mt][nt][e] = 0.f;

#pragma unroll
        for (int kt = 0; kt < 8; kt++) {
            const uint4* pa = (const uint4*)(WH + (size_t)(((w * 8 + kt) * 32 + lane) * 8));
            uint4 A0 = __ldg(pa);
            uint4 A1 = __ldg(pa + 1);
            u32 bh[4][2], bl[4][2];
#pragma unroll
            for (int nt = 0; nt < 4; nt++) {
                bh[nt][0] = bhi[bidx(kt, nt, 0, lane)];
                bh[nt][1] = bhi[bidx(kt, nt, 1, lane)];
                bl[nt][0] = blo[bidx(kt, nt, 0, lane)];
                bl[nt][1] = blo[bidx(kt, nt, 1, lane)];
            }
#pragma unroll
            for (int nt = 0; nt < 4; nt++) {
                mma16816(d[0][nt], A0.x, A0.y, A0.z, A0.w, bh[nt][0], bh[nt][1]);
                mma16816(d[1][nt], A1.x, A1.y, A1.z, A1.w, bh[nt][0], bh[nt][1]);
                mma16816(d[0][nt], A0.x, A0.y, A0.z, A0.w, bl[nt][0], bl[nt][1]);
                mma16816(d[1][nt], A1.x, A1.y, A1.z, A1.w, bl[nt][0], bl[nt][1]);
            }
            const uint4* pl = (const uint4*)(WL + (size_t)(((w * 8 + kt) * 32 + lane) * 8));
            uint4 L0 = __ldg(pl);
            uint4 L1 = __ldg(pl + 1);
#pragma unroll
            for (int nt = 0; nt < 4; nt++) {
                mma16816(d[0][nt], L0.x, L0.y, L0.z, L0.w, bh[nt][0], bh[nt][1]);
                mma16816(d[1][nt], L1.x, L1.y, L1.z, L1.w, bh[nt][0], bh[nt][1]);
            }
        }

        // ---- bias + relu -> vmat[p][j] -----------------------------------
        const float* bias = layer ? b2 : b1;
#pragma unroll
        for (int mt = 0; mt < 2; mt++) {
            int j0 = w * 32 + mt * 16 + g;
            float bA = __ldg(bias + j0);
            float bB = __ldg(bias + j0 + 8);
#pragma unroll
            for (int nt = 0; nt < 4; nt++) {
                int p0 = nt * 8 + tg * 2;
                vmat[p0 * VROW + j0]           = fmaxf(d[mt][nt][0] + bA, 0.f);
                vmat[(p0 + 1) * VROW + j0]     = fmaxf(d[mt][nt][1] + bA, 0.f);
                vmat[p0 * VROW + j0 + 8]       = fmaxf(d[mt][nt][2] + bB, 0.f);
                vmat[(p0 + 1) * VROW + j0 + 8] = fmaxf(d[mt][nt][3] + bB, 0.f);
            }
        }
        __syncthreads();

        // ---- LayerNorm: thread group of 4 per point ------------------------
        const int p  = tid >> 2;
        const int q4 = tid & 3;
        float v[32];
        float s1 = 0.f, s2 = 0.f;
        const float4* row = (const float4*)(vmat + p * VROW + q4 * 32);
#pragma unroll
        for (int i8 = 0; i8 < 8; i8++) {
            float4 t = row[i8];
            v[4 * i8] = t.x; v[4 * i8 + 1] = t.y; v[4 * i8 + 2] = t.z; v[4 * i8 + 3] = t.w;
            s1 += (t.x + t.y) + (t.z + t.w);
            s2 += (t.x * t.x + t.y * t.y) + (t.z * t.z + t.w * t.w);
        }
        s1 += __shfl_xor_sync(0xffffffffu, s1, 1);
        s1 += __shfl_xor_sync(0xffffffffu, s1, 2);
        s2 += __shfl_xor_sync(0xffffffffu, s2, 1);
        s2 += __shfl_xor_sync(0xffffffffu, s2, 2);
        float m   = s1 * (1.f / HID);
        float var = s2 * (1.f / HID) - m * m;
        float rs  = rsqrtf(var + 1e-5f);

        const float* gg = (layer ? g2 : g1) + q4 * 32;
        const float* bb = (layer ? bt2 : bt1) + q4 * 32;

        if (layer == 0) {
            // write normalized h1 -> bfrag for layer 2 (k index = j)
#pragma unroll
            for (int mm = 0; mm < 16; mm++) {
                float x0 = (v[2 * mm]     - m) * rs * __ldg(gg + 2 * mm)     + __ldg(bb + 2 * mm);
                float x1 = (v[2 * mm + 1] - m) * rs * __ldg(gg + 2 * mm + 1) + __ldg(bb + 2 * mm + 1);
                int kp = q4 * 16 + mm;
                int kt = kp >> 3, qq = kp & 7, reg = qq >> 2, tgq = qq & 3;
                u32 hp, lp;
                split2(x0, x1, hp, lp);
                int idx = bidx(kt, p >> 3, reg, (p & 7) * 4 + tgq);
                bhi[idx] = hp;
                blo[idx] = lp;
            }
            __syncthreads();
        } else {
            float part = 0.f;
#pragma unroll
            for (int i = 0; i < 32; i++) {
                float x = (v[i] - m) * rs * __ldg(gg + i) + __ldg(bb + i);
                part = fmaf(x, __ldg(w3 + q4 * 32 + i), part);
            }
            part += __shfl_xor_sync(0xffffffffu, part, 1);
            part += __shfl_xor_sync(0xffffffffu, part, 2);
            if (q4 == 0) {
                int po = base + p;
                if (po < B) out[po] = part + __ldg(b3);
            }
        }
    }
}

extern "C" void kernel_launch(void* const* d_in, const int* in_sizes, int n_in,
                              void* d_out, int out_size) {
    const float4* coords = (const float4*)d_in[0];
    const float2* stab   = (const float2*)d_in[1];
    const float2* ttab   = (const float2*)d_in[2];
    const float*  w1     = (const float*)d_in[3];
    const float*  b1     = (const float*)d_in[4];
    const float*  g1     = (const float*)d_in[5];
    const float*  be1    = (const float*)d_in[6];
    const float*  w2     = (const float*)d_in[7];
    const float*  b2     = (const float*)d_in[8];
    const float*  g2     = (const float*)d_in[9];
    const float*  be2    = (const float*)d_in[10];
    const float*  w3     = (const float*)d_in[11];
    const float*  b3     = (const float*)d_in[12];
    float* out = (float*)d_out;

    int B = in_sizes[0] / 4;
    if (B > MAXB) B = MAXB;
    int blocks = (B + P - 1) / P;

    setup_kernel<<<128, 256>>>(w1, w2);
    encode_kernel<<<blocks, 256>>>(coords, stab, ttab, B);
    mlp_mma_kernel<<<blocks, 128>>>(b1, g1, be1, b2, g2, be2, w3, b3, out, B);
}

// round 7
// speedup vs baseline: 1.9445x; 1.3758x over previous
#include <cuda_runtime.h>
#include <cuda_bf16.h>
#include <math.h>

typedef unsigned long long ull;
typedef unsigned int u32;

#define SL 36
#define TL 20
#define SENT (1u << 19)
#define TENT (1u << 17)
#define SMASK (SENT - 1u)
#define TMASK (TENT - 1u)
#define HID 128
#define ENC 112
#define NSLOT (SL + TL)
#define P 32
#define MAXB 131072
#define VROW 132

// weights pre-arranged in mma fragment order:
// [w(4)][kt(8)][lane(32)][mt(2) x areg(4)] u32 (bf16 pairs)
__device__ __align__(16) u32 g_w1hi[4 * 8 * 32 * 8];
__device__ __align__(16) u32 g_w1lo[4 * 8 * 32 * 8];
__device__ __align__(16) u32 g_w2hi[4 * 8 * 32 * 8];
__device__ __align__(16) u32 g_w2lo[4 * 8 * 32 * 8];
__device__ float g_res[NSLOT];

// ---- fp32x2 helpers ---------------------------------------------------------
__device__ __forceinline__ ull splat2(float v) {
    ull r; asm("mov.b64 %0, {%1, %1};" : "=l"(r) : "f"(v)); return r;
}
__device__ __forceinline__ float2 unpack2(ull v) {
    float2 r; asm("mov.b64 {%0, %1}, %2;" : "=f"(r.x), "=f"(r.y) : "l"(v)); return r;
}
__device__ __forceinline__ ull fma2(ull a, ull b, ull c) {
    ull d; asm("fma.rn.f32x2 %0, %1, %2, %3;" : "=l"(d) : "l"(a), "l"(b), "l"(c)); return d;
}
__device__ __forceinline__ ull mul2(ull a, ull b) {
    ull d; asm("mul.rn.f32x2 %0, %1, %2;" : "=l"(d) : "l"(a), "l"(b)); return d;
}

// ---- bf16 split / mma helpers ------------------------------------------------
__device__ __forceinline__ void split2(float x0, float x1, u32& hp, u32& lp) {
    __nv_bfloat16 h0 = __float2bfloat16(x0);
    __nv_bfloat16 h1 = __float2bfloat16(x1);
    __nv_bfloat16 l0 = __float2bfloat16(x0 - __bfloat162float(h0));
    __nv_bfloat16 l1 = __float2bfloat16(x1 - __bfloat162float(h1));
    hp = ((u32)__bfloat16_as_ushort(h1) << 16) | __bfloat16_as_ushort(h0);
    lp = ((u32)__bfloat16_as_ushort(l1) << 16) | __bfloat16_as_ushort(l0);
}

__device__ __forceinline__ void mma16816(float* d, u32 a0, u32 a1, u32 a2, u32 a3,
                                         u32 b0, u32 b1) {
    asm volatile(
        "mma.sync.aligned.m16n8k16.row.col.f32.bf16.bf16.f32 "
        "{%0,%1,%2,%3}, {%4,%5,%6,%7}, {%8,%9}, {%0,%1,%2,%3};"
        : "+f"(d[0]), "+f"(d[1]), "+f"(d[2]), "+f"(d[3])
        : "r"(a0), "r"(a1), "r"(a2), "r"(a3), "r"(b0), "r"(b1));
}

// bfrag index: [kt][nt][reg][lane]
__device__ __forceinline__ int bidx(int kt, int nt, int reg, int lane) {
    return ((kt * 4 + nt) * 2 + reg) * 32 + lane;
}

// ============================================================================
// setup kernel: weights -> bf16 hi/lo in fragment order + level resolutions.
// ============================================================================
__global__ void setup_kernel(const float* __restrict__ w1, const float* __restrict__ w2) {
    int t = blockIdx.x * blockDim.x + threadIdx.x;
    if (blockIdx.x == 0 && threadIdx.x < NSLOT) {
        int s = threadIdx.x;
        double bs = (s < SL) ? (double)1.38f : (double)1.5f;
        int e = (s < SL) ? s : s - SL;
        g_res[s] = floorf(16.0f * (float)pow(bs, (double)e));
    }
    int r     = t & 7;
    int lane  = (t >> 3) & 31;
    int kt    = (t >> 8) & 7;
    int w     = (t >> 11) & 3;
    int half  = (t >> 13) & 1;
    int layer = (t >> 14) & 1;
    int g  = lane >> 2;
    int tg = lane & 3;
    int mt = r >> 2;
    int rr = r & 3;
    int j  = w * 32 + mt * 16 + g + ((rr & 1) ? 8 : 0);
    int k0 = kt * 16 + tg * 2 + ((rr >> 1) ? 8 : 0);
    int k1 = k0 + 1;
    const float* W = layer ? w2 : w1;
    float x0 = (layer || k0 < ENC) ? W[k0 * HID + j] : 0.f;
    float x1 = (layer || k1 < ENC) ? W[k1 * HID + j] : 0.f;
    u32 hp, lp;
    split2(x0, x1, hp, lp);
    int idx = ((w * 8 + kt) * 32 + lane) * 8 + r;
    u32 val = half ? lp : hp;
    if (layer == 0) { if (half) g_w1lo[idx] = val; else g_w1hi[idx] = val; }
    else            { if (half) g_w2lo[idx] = val; else g_w2hi[idx] = val; }
}

// ============================================================================
// Fused kernel: encode 32 points directly into bf16 B-fragments, then
// 3-term bf16 mma MLP. 128 threads. smem: bfrag (16KB) unioned with
// vmat (16.9KB LN transpose buffer).
// ============================================================================
__global__ __launch_bounds__(128, 6)
void fused_kernel(const float4* __restrict__ coords,
                  const float2* __restrict__ stab,
                  const float2* __restrict__ ttab,
                  const float* __restrict__ b1, const float* __restrict__ g1,
                  const float* __restrict__ bt1,
                  const float* __restrict__ b2, const float* __restrict__ g2,
                  const float* __restrict__ bt2,
                  const float* __restrict__ w3, const float* __restrict__ b3,
                  float* __restrict__ out, int B)
{
    __shared__ __align__(16) unsigned char smraw[32 * VROW * 4];  // 16896 B
    u32* bhi = (u32*)smraw;            // [2048] (8KB)
    u32* blo = bhi + 2048;             // [2048] (8KB)
    float* vmat = (float*)smraw;       // overlays bfrag after mma completes

    const int tid  = threadIdx.x;
    const int w    = tid >> 5;
    const int lane = tid & 31;
    const int base = blockIdx.x * P;

    // zero pad rows kp=56..63 (kt=7): 256 u32 each
    bhi[1792 + tid] = 0u; bhi[1920 + tid] = 0u;
    blo[1792 + tid] = 0u; blo[1920 + tid] = 0u;

    // ---------------------------------------------------------------- encode
    int pi = base + lane;
    if (pi >= B) pi = B - 1;
    const float4 c = __ldg(&coords[pi]);

#pragma unroll 1
    for (int i = 0; i < 14; i++) {
        int s = w + 4 * i;               // warp-uniform level
        float2 a;
        if (s < SL) {
            float r = __ldg(&g_res[s]);
            float x = c.x * r, y = c.y * r, z = c.z * r;
            float fx = floorf(x), fy = floorf(y), fz = floorf(z);
            float wx = x - fx, wy = y - fy, wz = z - fz;
            float mx = 1.f - wx, my = 1.f - wy, mz = 1.f - wz;
            unsigned ux = (unsigned)fx, uy = (unsigned)fy, uz = (unsigned)fz;
            unsigned hx0 = ux, hx1 = ux + 1u;
            unsigned hy0 = uy * 2654435761u, hy1 = (uy + 1u) * 2654435761u;
            unsigned hz0 = uz * 805459861u,  hz1 = (uz + 1u) * 805459861u;
            float mymz = my * mz, wymz = wy * mz, mywz = my * wz, wywz = wy * wz;
            const float2* tb = stab + (size_t)s * SENT;
            ull f0 = *(const ull*)(tb + (((hx0 ^ hy0 ^ hz0) & SMASK)));
            ull f1 = *(const ull*)(tb + (((hx1 ^ hy0 ^ hz0) & SMASK)));
            ull f2 = *(const ull*)(tb + (((hx0 ^ hy1 ^ hz0) & SMASK)));
            ull f3 = *(const ull*)(tb + (((hx1 ^ hy1 ^ hz0) & SMASK)));
            ull f4 = *(const ull*)(tb + (((hx0 ^ hy0 ^ hz1) & SMASK)));
            ull f5 = *(const ull*)(tb + (((hx1 ^ hy0 ^ hz1) & SMASK)));
            ull f6 = *(const ull*)(tb + (((hx0 ^ hy1 ^ hz1) & SMASK)));
            ull f7 = *(const ull*)(tb + (((hx1 ^ hy1 ^ hz1) & SMASK)));
            ull acc = mul2(f0, splat2(mx * mymz));
            acc = fma2(f1, splat2(wx * mymz), acc);
            acc = fma2(f2, splat2(mx * wymz), acc);
            acc = fma2(f3, splat2(wx * wymz), acc);
            acc = fma2(f4, splat2(mx * mywz), acc);
            acc = fma2(f5, splat2(wx * mywz), acc);
            acc = fma2(f6, splat2(mx * wywz), acc);
            acc = fma2(f7, splat2(wx * wywz), acc);
            a = unpack2(acc);
        } else {
            int l = s - SL;
            float r  = __ldg(&g_res[s]);
            float tx = c.w * r;
            float tf = floorf(tx);
            float tw = tx - tf;
            unsigned t0 = (unsigned)tf;
            const float2* tb = ttab + (size_t)l * TENT;
            ull f0 = *(const ull*)(tb + (t0 & TMASK));
            ull f1 = *(const ull*)(tb + ((t0 + 1u) & TMASK));
            ull acc = mul2(f0, splat2(1.f - tw));
            acc = fma2(f1, splat2(tw), acc);
            a = unpack2(acc);
        }
        // level s == k-pair row s; point = lane. Write straight into fragments.
        u32 hp, lp;
        split2(a.x, a.y, hp, lp);
        int kt = s >> 3, qq = s & 7, reg = qq >> 2, tgq = qq & 3;
        int idx = bidx(kt, lane >> 3, reg, (lane & 7) * 4 + tgq);
        bhi[idx] = hp;
        blo[idx] = lp;
    }
    __syncthreads();

    // ---------------------------------------------------------------- MLP
#pragma unroll 1
    for (int layer = 0; layer < 2; layer++) {
        const u32* WH = layer ? g_w2hi : g_w1hi;
        const u32* WL = layer ? g_w2lo : g_w1lo;

        float d[2][4][4];
#pragma unroll
        for (int mt = 0; mt < 2; mt++)
#pragma unroll
            for (int nt = 0; nt < 4; nt++)
#pragma unroll
                for (int e = 0; e < 4; e++) d[mt][nt][e] = 0.f;

#pragma unroll
        for (int kt = 0; kt < 8; kt++) {
            const uint4* pa = (const uint4*)(WH + (size_t)(((w * 8 + kt) * 32 + lane) * 8));
            uint4 A0 = __ldg(pa);
            uint4 A1 = __ldg(pa + 1);
            u32 bh[4][2], bl[4][2];
#pragma unroll
            for (int nt = 0; nt < 4; nt++) {
                bh[nt][0] = bhi[bidx(kt, nt, 0, lane)];
                bh[nt][1] = bhi[bidx(kt, nt, 1, lane)];
                bl[nt][0] = blo[bidx(kt, nt, 0, lane)];
                bl[nt][1] = blo[bidx(kt, nt, 1, lane)];
            }
#pragma unroll
            for (int nt = 0; nt < 4; nt++) {
                mma16816(d[0][nt], A0.x, A0.y, A0.z, A0.w, bh[nt][0], bh[nt][1]);
                mma16816(d[1][nt], A1.x, A1.y, A1.z, A1.w, bh[nt][0], bh[nt][1]);
                mma16816(d[0][nt], A0.x, A0.y, A0.z, A0.w, bl[nt][0], bl[nt][1]);
                mma16816(d[1][nt], A1.x, A1.y, A1.z, A1.w, bl[nt][0], bl[nt][1]);
            }
            const uint4* pl = (const uint4*)(WL + (size_t)(((w * 8 + kt) * 32 + lane) * 8));
            uint4 L0 = __ldg(pl);
            uint4 L1 = __ldg(pl + 1);
#pragma unroll
            for (int nt = 0; nt < 4; nt++) {
                mma16816(d[0][nt], L0.x, L0.y, L0.z, L0.w, bh[nt][0], bh[nt][1]);
                mma16816(d[1][nt], L1.x, L1.y, L1.z, L1.w, bh[nt][0], bh[nt][1]);
            }
        }
        __syncthreads();   // all fragment reads done before vmat overlays bfrag

        // ---- bias + relu -> vmat[p][j] (vmat overlays bfrag) ---------------
        const int g  = lane >> 2;
        const int tg = lane & 3;
        const float* bias = layer ? b2 : b1;
#pragma unroll
        for (int mt = 0; mt < 2; mt++) {
            int j0 = w * 32 + mt * 16 + g;
            float bA = __ldg(bias + j0);
            float bB = __ldg(bias + j0 + 8);
#pragma unroll
            for (int nt = 0; nt < 4; nt++) {
                int p0 = nt * 8 + tg * 2;
                vmat[p0 * VROW + j0]           = fmaxf(d[mt][nt][0] + bA, 0.f);
                vmat[(p0 + 1) * VROW + j0]     = fmaxf(d[mt][nt][1] + bA, 0.f);
                vmat[p0 * VROW + j0 + 8]       = fmaxf(d[mt][nt][2] + bB, 0.f);
                vmat[(p0 + 1) * VROW + j0 + 8] = fmaxf(d[mt][nt][3] + bB, 0.f);
            }
        }
        __syncthreads();

        // ---- LayerNorm: 4 threads per point --------------------------------
        const int p  = tid >> 2;
        const int q4 = tid & 3;
        float v[32];
        float s1 = 0.f, s2 = 0.f;
        const float4* row = (const float4*)(vmat + p * VROW + q4 * 32);
#pragma unroll
        for (int i8 = 0; i8 < 8; i8++) {
            float4 t = row[i8];
            v[4 * i8] = t.x; v[4 * i8 + 1] = t.y; v[4 * i8 + 2] = t.z; v[4 * i8 + 3] = t.w;
            s1 += (t.x + t.y) + (t.z + t.w);
            s2 += (t.x * t.x + t.y * t.y) + (t.z * t.z + t.w * t.w);
        }
        s1 += __shfl_xor_sync(0xffffffffu, s1, 1);
        s1 += __shfl_xor_sync(0xffffffffu, s1, 2);
        s2 += __shfl_xor_sync(0xffffffffu, s2, 1);
        s2 += __shfl_xor_sync(0xffffffffu, s2, 2);
        float m   = s1 * (1.f / HID);
        float var = s2 * (1.f / HID) - m * m;
        float rs  = rsqrtf(var + 1e-5f);

        const float* gg = (layer ? g2 : g1) + q4 * 32;
        const float* bb = (layer ? bt2 : bt1) + q4 * 32;

        if (layer == 0) {
            __syncthreads();   // vmat reads (v[]) complete before bfrag overwrite
#pragma unroll
            for (int mm = 0; mm < 16; mm++) {
                float x0 = (v[2 * mm]     - m) * rs * __ldg(gg + 2 * mm)     + __ldg(bb + 2 * mm);
                float x1 = (v[2 * mm + 1] - m) * rs * __ldg(gg + 2 * mm + 1) + __ldg(bb + 2 * mm + 1);
                int kp = q4 * 16 + mm;
                int kt = kp >> 3, qq = kp & 7, reg = qq >> 2, tgq = qq & 3;
                u32 hp, lp;
                split2(x0, x1, hp, lp);
                int idx = bidx(kt, p >> 3, reg, (p & 7) * 4 + tgq);
                bhi[idx] = hp;
                blo[idx] = lp;
            }
            __syncthreads();   // bfrag2 ready before layer-2 mma reads
        } else {
            float part = 0.f;
#pragma unroll
            for (int i = 0; i < 32; i++) {
                float x = (v[i] - m) * rs * __ldg(gg + i) + __ldg(bb + i);
                part = fmaf(x, __ldg(w3 + q4 * 32 + i), part);
            }
            part += __shfl_xor_sync(0xffffffffu, part, 1);
            part += __shfl_xor_sync(0xffffffffu, part, 2);
            if (q4 == 0) {
                int po = base + p;
                if (po < B) out[po] = part + __ldg(b3);
            }
        }
    }
}

extern "C" void kernel_launch(void* const* d_in, const int* in_sizes, int n_in,
                              void* d_out, int out_size) {
    const float4* coords = (const float4*)d_in[0];
    const float2* stab   = (const float2*)d_in[1];
    const float2* ttab   = (const float2*)d_in[2];
    const float*  w1     = (const float*)d_in[3];
    const float*  b1     = (const float*)d_in[4];
    const float*  g1     = (const float*)d_in[5];
    const float*  be1    = (const float*)d_in[6];
    const float*  w2     = (const float*)d_in[7];
    const float*  b2     = (const float*)d_in[8];
    const float*  g2     = (const float*)d_in[9];
    const float*  be2    = (const float*)d_in[10];
    const float*  w3     = (const float*)d_in[11];
    const float*  b3     = (const float*)d_in[12];
    float* out = (float*)d_out;

    int B = in_sizes[0] / 4;
    if (B > MAXB) B = MAXB;
    int blocks = (B + P - 1) / P;

    setup_kernel<<<128, 256>>>(w1, w2);
    fused_kernel<<<blocks, 128>>>(coords, stab, ttab,
                                  b1, g1, be1, b2, g2, be2, w3, b3, out, B);
}